// round 1
// baseline (speedup 1.0000x reference)
#include <cuda_runtime.h>
#include <math.h>

// Problem constants
#define D   784
#define H   500
#define HP  512          // H padded to 512 (zero-filled tail)
#define B   512
#define S   8            // segments over D
#define L   98           // D / S
#define BD  (B*D)

#define TPB      256     // threads per scan block
#define WPB      8       // warps per block
#define RPW      2       // batch rows per warp
#define ROWS_PB  (WPB*RPW)   // 16 rows per block

// Static device scratch (no allocations allowed)
__device__ float g_WT[D*HP];     // W transposed+padded: [d][h]
__device__ float g_Vp[D*HP];     // V padded:            [d][h]
__device__ float g_c [HP];       // c padded
__device__ float g_A [S*B*HP];   // checkpoint states a_{sL}: [s][b][h]

// ---------------------------------------------------------------------------
// K0: pack W^T and V into padded d-major layouts, pad c.
// ---------------------------------------------------------------------------
__global__ void k_pack(const float* __restrict__ W,
                       const float* __restrict__ V,
                       const float* __restrict__ c) {
    int d = blockIdx.x;          // 0..783
    int t = threadIdx.x;         // 0..511
    float wv = (t < H) ? W[t*D + d] : 0.0f;   // W is [H, D]
    float vv = (t < H) ? V[d*H + t] : 0.0f;   // V is [D, H]
    g_WT[d*HP + t] = wv;
    g_Vp[d*HP + t] = vv;
    if (d == 0) g_c[t] = (t < H) ? c[t] : 0.0f;
}

// ---------------------------------------------------------------------------
// K1: per-segment partial products P_s = X[:, sL:(s+1)L] @ W[sL:(s+1)L, :]
//     stored into g_A slot s+1 (slots 1..7). One block per (s, b).
// ---------------------------------------------------------------------------
__global__ void k_partial(const float* __restrict__ x) {
    int s = blockIdx.x;          // 0..6
    int b = blockIdx.y;          // 0..511
    int t = threadIdx.x;         // 0..127 : float4 group over HP
    const float4* WT4 = (const float4*)g_WT;
    const float*  xr  = x + b*D + s*L;
    float4 acc = make_float4(0.f, 0.f, 0.f, 0.f);
    for (int j = 0; j < L; j++) {
        float xv = xr[j];
        if (xv != 0.0f) {        // uniform across block: x[b,d] same for all t
            float4 w = WT4[(s*L + j)*128 + t];
            acc.x = fmaf(xv, w.x, acc.x);
            acc.y = fmaf(xv, w.y, acc.y);
            acc.z = fmaf(xv, w.z, acc.z);
            acc.w = fmaf(xv, w.w, acc.w);
        }
    }
    ((float4*)g_A)[((s+1)*B + b)*128 + t] = acc;
}

// ---------------------------------------------------------------------------
// K2: exclusive prefix over segments: A[s] = c + sum_{t<s} P_t
// ---------------------------------------------------------------------------
__global__ void k_prefix() {
    int b = blockIdx.x;          // 0..511
    int t = threadIdx.x;         // 0..127
    float4* A4 = (float4*)g_A;
    float4  v  = ((const float4*)g_c)[t];
    A4[(0*B + b)*128 + t] = v;
    for (int s = 1; s < S; s++) {
        float4 p = A4[(s*B + b)*128 + t];
        v.x += p.x; v.y += p.y; v.z += p.z; v.w += p.w;
        A4[(s*B + b)*128 + t] = v;
    }
}

// ---------------------------------------------------------------------------
// K3: the scan. Block = (segment s, row-block of 16 rows). Warp = 2 rows.
// Lane owns h = 4*lane + 128*k, k<4  (float4-coalesced V / W^T slices).
// ---------------------------------------------------------------------------
__global__ __launch_bounds__(TPB)
void k_scan(const float* __restrict__ x,
            const float* __restrict__ u,
            const float* __restrict__ bvec,
            float* __restrict__ out) {
    int s    = blockIdx.x;       // 0..7
    int rb   = blockIdx.y;       // 0..31
    int tid  = threadIdx.x;
    int w    = tid >> 5;
    int lane = tid & 31;
    int rowbase = rb * ROWS_PB;

    __shared__ float sx[ROWS_PB * L];
    __shared__ float su[ROWS_PB * L];
    __shared__ float sb[L];

    // Stage x, u, b slices for this block's rows / segment
    for (int i = tid; i < ROWS_PB * L; i += TPB) {
        int r = i / L, j = i - r * L;
        sx[i] = x[(rowbase + r)*D + s*L + j];
        su[i] = u[(rowbase + r)*D + s*L + j];
    }
    for (int i = tid; i < L; i += TPB) sb[i] = bvec[s*L + i];
    __syncthreads();

    int r0 = rowbase + w * RPW;          // global row for lane-0 output
    const float4* A4 = (const float4*)g_A;
    float4 a0[4], a1[4];
    #pragma unroll
    for (int k = 0; k < 4; k++) {
        a0[k] = A4[(s*B + r0    )*128 + lane + 32*k];
        a1[k] = A4[(s*B + r0 + 1)*128 + lane + 32*k];
    }

    const float4* V4 = (const float4*)g_Vp;
    const float4* W4 = (const float4*)g_WT;
    const float* sx0 = sx + (w*RPW    )*L;
    const float* sx1 = sx + (w*RPW + 1)*L;
    const float* su0 = su + (w*RPW    )*L;
    const float* su1 = su + (w*RPW + 1)*L;

    int dbase = s * L;
    #pragma unroll 2
    for (int j = 0; j < L; j++) {
        int d = dbase + j;
        const float4* Vr = V4 + d*128;
        const float4* Wr = W4 + d*128;
        float x0 = sx0[j], x1 = sx1[j];

        float dot0 = 0.f, dot1 = 0.f;
        #pragma unroll
        for (int k = 0; k < 4; k++) {
            float4 v  = Vr[lane + 32*k];
            float4 h0 = a0[k];
            float4 h1 = a1[k];
            dot0 += fmaxf(h0.x,0.f)*v.x + fmaxf(h0.y,0.f)*v.y
                  + fmaxf(h0.z,0.f)*v.z + fmaxf(h0.w,0.f)*v.w;
            dot1 += fmaxf(h1.x,0.f)*v.x + fmaxf(h1.y,0.f)*v.y
                  + fmaxf(h1.z,0.f)*v.z + fmaxf(h1.w,0.f)*v.w;
        }

        // Rank-1 state update; x0/x1 are warp-uniform -> uniform branch
        if (x0 != 0.0f || x1 != 0.0f) {
            #pragma unroll
            for (int k = 0; k < 4; k++) {
                float4 wv = Wr[lane + 32*k];
                a0[k].x = fmaf(x0, wv.x, a0[k].x);
                a0[k].y = fmaf(x0, wv.y, a0[k].y);
                a0[k].z = fmaf(x0, wv.z, a0[k].z);
                a0[k].w = fmaf(x0, wv.w, a0[k].w);
                a1[k].x = fmaf(x1, wv.x, a1[k].x);
                a1[k].y = fmaf(x1, wv.y, a1[k].y);
                a1[k].z = fmaf(x1, wv.z, a1[k].z);
                a1[k].w = fmaf(x1, wv.w, a1[k].w);
            }
        }

        // Butterfly reduce both dots across the warp
        #pragma unroll
        for (int off = 16; off > 0; off >>= 1) {
            dot0 += __shfl_xor_sync(0xffffffffu, dot0, off);
            dot1 += __shfl_xor_sync(0xffffffffu, dot1, off);
        }

        // Epilogue: lanes 0,1 handle rows r0, r0+1
        if (lane < 2) {
            float lv = (lane == 0 ? dot0 : dot1) + sb[j];
            float uu = (lane == 0 ? su0[j] : su1[j]);
            float p  = 1.0f / (1.0f + expf(-lv));
            float xs = (uu < p) ? 1.0f : 0.0f;
            int g = r0 + lane;
            out[      g*D + d] = lv;
            out[BD + g*D + d] = xs;
        }
    }
}

// ---------------------------------------------------------------------------
// Inputs (metadata order): x[B,D], u[B,D], W[H,D], c[H], V[D,H], b[D]
// Output: [ l (B*D floats) | x_sample (B*D floats) ]
// ---------------------------------------------------------------------------
extern "C" void kernel_launch(void* const* d_in, const int* in_sizes, int n_in,
                              void* d_out, int out_size) {
    (void)in_sizes; (void)n_in; (void)out_size;
    const float* x    = (const float*)d_in[0];
    const float* u    = (const float*)d_in[1];
    const float* W    = (const float*)d_in[2];
    const float* c    = (const float*)d_in[3];
    const float* V    = (const float*)d_in[4];
    const float* bvec = (const float*)d_in[5];
    float* out = (float*)d_out;

    k_pack   <<<D, HP>>>(W, V, c);
    k_partial<<<dim3(S-1, B), 128>>>(x);
    k_prefix <<<B, 128>>>();
    k_scan   <<<dim3(S, B/ROWS_PB), TPB>>>(x, u, bvec, out);
}

// round 4
// speedup vs baseline: 1.1069x; 1.1069x over previous
#include <cuda_runtime.h>
#include <math.h>

// Problem constants
#define D   784
#define H   500
#define HP  512          // H padded to 512 (zero tail)
#define B   512
#define S   28           // segments over D (784 = 28*28)
#define L   28           // steps per segment
#define BD  (B*D)

#define TPB      256     // threads per scan block
#define WPB      8       // warps per block
#define RPW      2       // batch rows per warp
#define ROWS_PB  (WPB*RPW)   // 16 rows per block
#define CH       4       // reduction chunk (L = 7*CH)

typedef unsigned long long u64;

// Static device scratch
__device__ float g_WT[D*HP];     // W^T padded: [d][h]
__device__ float g_Vp[D*HP];     // V padded:   [d][h]
__device__ float g_c [HP];
__device__ float g_A [S*B*HP];   // checkpoints a_{sL}: [s][b][h]

// ---- packed f32x2 helpers -------------------------------------------------
__device__ __forceinline__ u64 ffma2(u64 a, u64 b, u64 c) {
    u64 d;
    asm("fma.rn.f32x2 %0, %1, %2, %3;" : "=l"(d) : "l"(a), "l"(b), "l"(c));
    return d;
}
__device__ __forceinline__ u64 relu2(u64 a) {
    u64 r;
    asm("{\n\t.reg .f32 lo, hi;\n\t"
        "mov.b64 {lo, hi}, %1;\n\t"
        "max.f32 lo, lo, 0f00000000;\n\t"
        "max.f32 hi, hi, 0f00000000;\n\t"
        "mov.b64 %0, {lo, hi};\n\t}" : "=l"(r) : "l"(a));
    return r;
}
__device__ __forceinline__ u64 pack2(float x) {
    u64 r;
    asm("mov.b64 %0, {%1, %1};" : "=l"(r) : "f"(x));
    return r;
}
__device__ __forceinline__ float hadd2(u64 a) {
    float lo, hi;
    asm("mov.b64 {%0, %1}, %2;" : "=f"(lo), "=f"(hi) : "l"(a));
    return lo + hi;
}

// ---------------------------------------------------------------------------
// K0: pack W^T and V into padded d-major layouts, pad c.
// ---------------------------------------------------------------------------
__global__ void k_pack(const float* __restrict__ W,
                       const float* __restrict__ V,
                       const float* __restrict__ c) {
    int d = blockIdx.x;
    int t = threadIdx.x;
    float wv = (t < H) ? W[t*D + d] : 0.0f;   // W is [H, D]
    float vv = (t < H) ? V[d*H + t] : 0.0f;   // V is [D, H]
    g_WT[d*HP + t] = wv;
    g_Vp[d*HP + t] = vv;
    if (d == 0) g_c[t] = (t < H) ? c[t] : 0.0f;
}

// ---------------------------------------------------------------------------
// K1: fused partial+prefix. Block b scans all of d, writing the running state
//     to g_A at every segment boundary. x in {0,1} -> conditional adds.
// ---------------------------------------------------------------------------
__global__ __launch_bounds__(128)
void k_states(const float* __restrict__ x) {
    int b = blockIdx.x;          // 0..511
    int t = threadIdx.x;         // 0..127 : float4 chunk over HP
    const float4* WT4 = (const float4*)g_WT;
    const float4* xr4 = (const float4*)(x + b*D);
    float4* A4 = (float4*)g_A;

    float4 acc = ((const float4*)g_c)[t];
    int s = 0;
    #pragma unroll 7
    for (int d4 = 0; d4 < D/4; d4++) {
        if ((d4 % (L/4)) == 0) {             // d4*4 % 28 == 0
            A4[(s*B + b)*128 + t] = acc;
            s++;
        }
        float4 xq = xr4[d4];
        if (xq.x != 0.0f) { float4 w = WT4[(d4*4+0)*128 + t];
            acc.x += w.x; acc.y += w.y; acc.z += w.z; acc.w += w.w; }
        if (xq.y != 0.0f) { float4 w = WT4[(d4*4+1)*128 + t];
            acc.x += w.x; acc.y += w.y; acc.z += w.z; acc.w += w.w; }
        if (xq.z != 0.0f) { float4 w = WT4[(d4*4+2)*128 + t];
            acc.x += w.x; acc.y += w.y; acc.z += w.z; acc.w += w.w; }
        if (xq.w != 0.0f) { float4 w = WT4[(d4*4+3)*128 + t];
            acc.x += w.x; acc.y += w.y; acc.z += w.z; acc.w += w.w; }
    }
}

// ---------------------------------------------------------------------------
// K2: the scan. Block = (segment s, 16 rows). Warp = 2 rows.
// Lane owns 4 ulonglong2 (16 floats) of the 512-wide state, packed f32x2.
// Reductions batched over CH=4 steps; outputs staged in smem.
// ---------------------------------------------------------------------------
__global__ __launch_bounds__(TPB, 3)
void k_scan(const float* __restrict__ x,
            const float* __restrict__ u,
            const float* __restrict__ bvec,
            float* __restrict__ out) {
    int s    = blockIdx.x;       // 0..27
    int rb   = blockIdx.y;       // 0..31
    int tid  = threadIdx.x;
    int w    = tid >> 5;
    int lane = tid & 31;
    int rowbase = rb * ROWS_PB;

    __shared__ float sx [ROWS_PB * L];
    __shared__ float su [ROWS_PB * L];
    __shared__ float sb [L];
    __shared__ float sl [ROWS_PB * L];
    __shared__ float sxs[ROWS_PB * L];

    for (int i = tid; i < ROWS_PB * L; i += TPB) {
        int r = i / L, j = i - r * L;
        sx[i] = x[(rowbase + r)*D + s*L + j];
        su[i] = u[(rowbase + r)*D + s*L + j];
    }
    for (int i = tid; i < L; i += TPB) sb[i] = bvec[s*L + i];
    __syncthreads();

    int r0 = rowbase + w * RPW;
    // state as packed pairs: row = 128 ulonglong2; lane owns idx lane+32*k, k<4
    const ulonglong2* A2 = (const ulonglong2*)g_A;
    u64 a0[8], a1[8];
    #pragma unroll
    for (int k = 0; k < 4; k++) {
        ulonglong2 q0 = A2[(size_t)(s*B + r0    )*128 + lane + 32*k];
        ulonglong2 q1 = A2[(size_t)(s*B + r0 + 1)*128 + lane + 32*k];
        a0[2*k] = q0.x; a0[2*k+1] = q0.y;
        a1[2*k] = q1.x; a1[2*k+1] = q1.y;
    }

    const ulonglong2* V2 = (const ulonglong2*)g_Vp;
    const ulonglong2* W2 = (const ulonglong2*)g_WT;
    const float* sx0 = sx + (w*RPW    )*L;
    const float* sx1 = sx + (w*RPW + 1)*L;
    const float* su0 = su + (w*RPW    )*L;
    const float* su1 = su + (w*RPW + 1)*L;
    float* sl0  = sl  + (w*RPW)*L;
    float* sxs0 = sxs + (w*RPW)*L;

    int dbase = s * L;
    for (int c4 = 0; c4 < L/CH; c4++) {
        float d0[CH], d1[CH];
        #pragma unroll
        for (int jj = 0; jj < CH; jj++) {
            int j = c4*CH + jj;
            int d = dbase + j;
            const ulonglong2* Vr = V2 + (size_t)d*128;
            const ulonglong2* Wr = W2 + (size_t)d*128;
            float x0 = sx0[j], x1 = sx1[j];

            u64 dp0 = 0ull, dp1 = 0ull;
            #pragma unroll
            for (int k = 0; k < 4; k++) {
                ulonglong2 vq = Vr[lane + 32*k];
                dp0 = ffma2(relu2(a0[2*k  ]), vq.x, dp0);
                dp0 = ffma2(relu2(a0[2*k+1]), vq.y, dp0);
                dp1 = ffma2(relu2(a1[2*k  ]), vq.x, dp1);
                dp1 = ffma2(relu2(a1[2*k+1]), vq.y, dp1);
            }
            if (x0 != 0.0f || x1 != 0.0f) {   // warp-uniform branch
                u64 xx0 = pack2(x0), xx1 = pack2(x1);
                #pragma unroll
                for (int k = 0; k < 4; k++) {
                    ulonglong2 wq = Wr[lane + 32*k];
                    a0[2*k  ] = ffma2(xx0, wq.x, a0[2*k  ]);
                    a0[2*k+1] = ffma2(xx0, wq.y, a0[2*k+1]);
                    a1[2*k  ] = ffma2(xx1, wq.x, a1[2*k  ]);
                    a1[2*k+1] = ffma2(xx1, wq.y, a1[2*k+1]);
                }
            }
            d0[jj] = hadd2(dp0);
            d1[jj] = hadd2(dp1);
        }

        // 8 independent butterfly chains
        #pragma unroll
        for (int off = 16; off > 0; off >>= 1) {
            #pragma unroll
            for (int jj = 0; jj < CH; jj++) {
                d0[jj] += __shfl_xor_sync(0xffffffffu, d0[jj], off);
                d1[jj] += __shfl_xor_sync(0xffffffffu, d1[jj], off);
            }
        }

        // epilogue: lanes 0..2*CH-1 each handle one (step, row)
        if (lane < 2*CH) {
            #pragma unroll
            for (int jj = 0; jj < CH; jj++) {
                if ((lane >> 1) == jj) {
                    int r = lane & 1;
                    int j = c4*CH + jj;
                    float dotv = r ? d1[jj] : d0[jj];
                    float lv   = dotv + sb[j];
                    float uu   = r ? su1[j] : su0[j];
                    float e    = expf(-lv);
                    float xs   = (fmaf(uu, e, uu) < 1.0f) ? 1.0f : 0.0f;
                    sl0 [r*L + j] = lv;
                    sxs0[r*L + j] = xs;
                }
            }
        }
    }

    __syncthreads();
    for (int i = tid; i < ROWS_PB * L; i += TPB) {
        int r = i / L, j = i - r * L;
        size_t g = (size_t)(rowbase + r)*D + s*L + j;
        out[g]      = sl[i];
        out[BD + g] = sxs[i];
    }
}

// ---------------------------------------------------------------------------
// Inputs: x[B,D], u[B,D], W[H,D], c[H], V[D,H], b[D]
// Output: [ l (B*D) | x_sample (B*D) ]
// ---------------------------------------------------------------------------
extern "C" void kernel_launch(void* const* d_in, const int* in_sizes, int n_in,
                              void* d_out, int out_size) {
    (void)in_sizes; (void)n_in; (void)out_size;
    const float* x    = (const float*)d_in[0];
    const float* u    = (const float*)d_in[1];
    const float* W    = (const float*)d_in[2];
    const float* c    = (const float*)d_in[3];
    const float* V    = (const float*)d_in[4];
    const float* bvec = (const float*)d_in[5];
    float* out = (float*)d_out;

    k_pack  <<<D, HP>>>(W, V, c);
    k_states<<<B, 128>>>(x);
    k_scan  <<<dim3(S, B/ROWS_PB), TPB>>>(x, u, bvec, out);
}

// round 5
// speedup vs baseline: 1.3408x; 1.2113x over previous
#include <cuda_runtime.h>
#include <math.h>

// Problem constants
#define D   784
#define H   500
#define HP  512
#define B   512
#define S   28           // segments (784 = 28*28)
#define L   28           // steps per segment
#define BD  (B*D)

#define TPB      256
#define WPB      8
#define RPW      4       // rows per warp in k_scan
#define ROWS_PB  (WPB*RPW)   // 32
#define CH       2       // dot-reduction chunk

typedef unsigned long long u64;

// Static device scratch
__device__ float g_WT[D*HP];     // W^T padded: [d][h]
__device__ float g_Vp[D*HP];     // V padded:   [d][h]
__device__ float g_c [HP];
__device__ float g_A [S*B*HP];   // partials then checkpoints: [s][b][h]

// ---- packed f32x2 helpers -------------------------------------------------
__device__ __forceinline__ u64 ffma2(u64 a, u64 b, u64 c) {
    u64 d;
    asm("fma.rn.f32x2 %0, %1, %2, %3;" : "=l"(d) : "l"(a), "l"(b), "l"(c));
    return d;
}
__device__ __forceinline__ u64 relu2(u64 a) {
    u64 r;
    asm("{\n\t.reg .f32 lo, hi;\n\t"
        "mov.b64 {lo, hi}, %1;\n\t"
        "max.f32 lo, lo, 0f00000000;\n\t"
        "max.f32 hi, hi, 0f00000000;\n\t"
        "mov.b64 %0, {lo, hi};\n\t}" : "=l"(r) : "l"(a));
    return r;
}
__device__ __forceinline__ u64 pack2(float x) {
    u64 r;
    asm("mov.b64 %0, {%1, %1};" : "=l"(r) : "f"(x));
    return r;
}
__device__ __forceinline__ float hadd2(u64 a) {
    float lo, hi;
    asm("mov.b64 {%0, %1}, %2;" : "=f"(lo), "=f"(hi) : "l"(a));
    return lo + hi;
}

// ---------------------------------------------------------------------------
// K0a: pad V rows 500->512, pad c. Fully coalesced.
// ---------------------------------------------------------------------------
__global__ void k_packV(const float* __restrict__ V,
                        const float* __restrict__ c) {
    int d = blockIdx.x;          // 0..783
    int t = threadIdx.x;         // 0..511
    g_Vp[d*HP + t] = (t < H) ? V[d*H + t] : 0.0f;
    if (d == 0) g_c[t] = (t < H) ? c[t] : 0.0f;
}

// ---------------------------------------------------------------------------
// K0b: tiled transpose W [H,D] -> g_WT [D,HP]. 32x32 tiles via smem.
// ---------------------------------------------------------------------------
__global__ void k_packW(const float* __restrict__ W) {
    __shared__ float tile[32][33];
    int d0 = blockIdx.x * 32;    // 25 blocks -> covers 784 (800 guarded)
    int h0 = blockIdx.y * 32;    // 16 blocks -> 512
    int tx = threadIdx.x;        // 0..31
    int ty = threadIdx.y;        // 0..7
    #pragma unroll
    for (int i = 0; i < 4; i++) {
        int h = h0 + ty + 8*i;
        int d = d0 + tx;
        float v = 0.0f;
        if (h < H && d < D) v = W[h*D + d];
        tile[ty + 8*i][tx] = v;
    }
    __syncthreads();
    #pragma unroll
    for (int i = 0; i < 4; i++) {
        int d = d0 + ty + 8*i;
        int h = h0 + tx;
        if (d < D) g_WT[d*HP + h] = tile[tx][ty + 8*i];
    }
}

// ---------------------------------------------------------------------------
// K1: partial GEMM. Block = (segment s in 0..26, 32-row tile).
//     P_s[rows, :] = X[rows, s*28:(s+1)*28] @ W[s*28:(s+1)*28, :]
//     Thread owns one h-pair (u64), 32 row-accumulators. W row read once/block.
// ---------------------------------------------------------------------------
__global__ __launch_bounds__(256)
void k_partial(const float* __restrict__ x) {
    int s  = blockIdx.x;         // 0..26
    int rb = blockIdx.y;         // 0..15
    int t  = threadIdx.x;        // 0..255 : h-pair index
    int rowbase = rb * 32;

    __shared__ u64 sxp[32 * L];  // pre-packed x (f32x2 duplicated)
    for (int i = t; i < 32 * L; i += 256) {
        int r = i / L, j = i - r * L;
        sxp[i] = pack2(x[(rowbase + r)*D + s*L + j]);
    }
    __syncthreads();

    u64 acc[32];
    #pragma unroll
    for (int r = 0; r < 32; r++) acc[r] = 0ull;

    const u64* W1 = (const u64*)g_WT;   // 256 pairs per d-row
    #pragma unroll 2
    for (int j = 0; j < L; j++) {
        u64 wv = W1[(size_t)(s*L + j)*256 + t];
        #pragma unroll
        for (int r = 0; r < 32; r++)
            acc[r] = ffma2(sxp[r*L + j], wv, acc[r]);   // x in {0,1}: exact
    }

    u64* A1 = (u64*)g_A;
    #pragma unroll
    for (int r = 0; r < 32; r++)
        A1[(size_t)(s*B + rowbase + r)*256 + t] = acc[r];
}

// ---------------------------------------------------------------------------
// K2: prefix over segments: A[s] = c + sum_{t<s} P_t  (in-place, slot s holds
//     P_s before being overwritten with A_s; slot 27's stale read is dead).
// ---------------------------------------------------------------------------
__global__ __launch_bounds__(128)
void k_prefix() {
    int b = blockIdx.x;          // 0..511
    int t = threadIdx.x;         // 0..127
    float4* A4 = (float4*)g_A;
    float4  v  = ((const float4*)g_c)[t];
    #pragma unroll 4
    for (int s = 0; s < S; s++) {
        float4 p = A4[(size_t)(s*B + b)*128 + t];
        A4[(size_t)(s*B + b)*128 + t] = v;
        v.x += p.x; v.y += p.y; v.z += p.z; v.w += p.w;
    }
}

// ---------------------------------------------------------------------------
// K3: the scan. Block = (segment, 32 rows). Warp = 4 rows.
// Lane owns 16 floats (8 u64) of the 512-wide state per row.
// Updates unconditional (x=0 -> +0, exact); dot reductions batched CH=2.
// ---------------------------------------------------------------------------
__global__ __launch_bounds__(TPB, 2)
void k_scan(const float* __restrict__ x,
            const float* __restrict__ u,
            const float* __restrict__ bvec,
            float* __restrict__ out) {
    int s    = blockIdx.x;       // 0..27
    int rb   = blockIdx.y;       // 0..15
    int tid  = threadIdx.x;
    int w    = tid >> 5;
    int lane = tid & 31;
    int rowbase = rb * ROWS_PB;

    __shared__ u64   sxp[ROWS_PB * L];   // pre-packed x
    __shared__ float su [ROWS_PB * L];
    __shared__ float sb [L];
    __shared__ float sl [ROWS_PB * L];
    __shared__ float sxs[ROWS_PB * L];

    for (int i = tid; i < ROWS_PB * L; i += TPB) {
        int r = i / L, j = i - r * L;
        sxp[i] = pack2(x[(rowbase + r)*D + s*L + j]);
        su [i] = u[(rowbase + r)*D + s*L + j];
    }
    for (int i = tid; i < L; i += TPB) sb[i] = bvec[s*L + i];
    __syncthreads();

    int r0 = rowbase + w * RPW;
    const ulonglong2* A2 = (const ulonglong2*)g_A;
    u64 a[RPW][8];
    #pragma unroll
    for (int r = 0; r < RPW; r++) {
        #pragma unroll
        for (int k = 0; k < 4; k++) {
            ulonglong2 q = A2[(size_t)(s*B + r0 + r)*128 + lane + 32*k];
            a[r][2*k] = q.x; a[r][2*k+1] = q.y;
        }
    }

    const ulonglong2* V2 = (const ulonglong2*)g_Vp;
    const ulonglong2* W2 = (const ulonglong2*)g_WT;
    const u64* sxw = sxp + (w*RPW)*L;

    int dbase = s * L;
    for (int c2 = 0; c2 < L/CH; c2++) {
        float dt[RPW][CH];
        #pragma unroll
        for (int jj = 0; jj < CH; jj++) {
            int j = c2*CH + jj;
            int d = dbase + j;
            const ulonglong2* Vr = V2 + (size_t)d*128;
            const ulonglong2* Wr = W2 + (size_t)d*128;
            u64 xx[RPW];
            #pragma unroll
            for (int r = 0; r < RPW; r++) xx[r] = sxw[r*L + j];

            u64 dp[RPW];
            #pragma unroll
            for (int r = 0; r < RPW; r++) dp[r] = 0ull;

            #pragma unroll
            for (int k = 0; k < 4; k++) {
                ulonglong2 vq = Vr[lane + 32*k];
                ulonglong2 wq = Wr[lane + 32*k];
                #pragma unroll
                for (int r = 0; r < RPW; r++) {
                    dp[r] = ffma2(relu2(a[r][2*k  ]), vq.x, dp[r]);
                    dp[r] = ffma2(relu2(a[r][2*k+1]), vq.y, dp[r]);
                    a[r][2*k  ] = ffma2(xx[r], wq.x, a[r][2*k  ]);
                    a[r][2*k+1] = ffma2(xx[r], wq.y, a[r][2*k+1]);
                }
            }
            #pragma unroll
            for (int r = 0; r < RPW; r++) dt[r][jj] = hadd2(dp[r]);
        }

        // 8 independent butterfly chains
        #pragma unroll
        for (int off = 16; off > 0; off >>= 1) {
            #pragma unroll
            for (int r = 0; r < RPW; r++)
                #pragma unroll
                for (int jj = 0; jj < CH; jj++)
                    dt[r][jj] += __shfl_xor_sync(0xffffffffu, dt[r][jj], off);
        }

        // epilogue: lane k (<8) handles (row k>>1, step k&1)
        if (lane < RPW*CH) {
            int r  = lane >> 1;
            int jj = lane & 1;
            float dv = dt[0][0];
            dv = (lane == 1) ? dt[0][1] : dv;
            dv = (lane == 2) ? dt[1][0] : dv;
            dv = (lane == 3) ? dt[1][1] : dv;
            dv = (lane == 4) ? dt[2][0] : dv;
            dv = (lane == 5) ? dt[2][1] : dv;
            dv = (lane == 6) ? dt[3][0] : dv;
            dv = (lane == 7) ? dt[3][1] : dv;
            int j  = c2*CH + jj;
            int ri = w*RPW + r;
            float lv = dv + sb[j];
            float uu = su[ri*L + j];
            float e  = expf(-lv);
            float xs = (fmaf(uu, e, uu) < 1.0f) ? 1.0f : 0.0f;
            sl [ri*L + j] = lv;
            sxs[ri*L + j] = xs;
        }
    }

    __syncthreads();
    for (int i = tid; i < ROWS_PB * L; i += TPB) {
        int r = i / L, j = i - r * L;
        size_t g = (size_t)(rowbase + r)*D + s*L + j;
        out[g]      = sl[i];
        out[BD + g] = sxs[i];
    }
}

// ---------------------------------------------------------------------------
// Inputs: x[B,D], u[B,D], W[H,D], c[H], V[D,H], b[D]
// Output: [ l (B*D) | x_sample (B*D) ]
// ---------------------------------------------------------------------------
extern "C" void kernel_launch(void* const* d_in, const int* in_sizes, int n_in,
                              void* d_out, int out_size) {
    (void)in_sizes; (void)n_in; (void)out_size;
    const float* x    = (const float*)d_in[0];
    const float* u    = (const float*)d_in[1];
    const float* W    = (const float*)d_in[2];
    const float* c    = (const float*)d_in[3];
    const float* V    = (const float*)d_in[4];
    const float* bvec = (const float*)d_in[5];
    float* out = (float*)d_out;

    k_packV  <<<D, HP>>>(V, c);
    k_packW  <<<dim3((D+31)/32, HP/32), dim3(32, 8)>>>(W);
    k_partial<<<dim3(S-1, B/32), 256>>>(x);
    k_prefix <<<B, 128>>>();
    k_scan   <<<dim3(S, B/ROWS_PB), TPB>>>(x, u, bvec, out);
}

// round 6
// speedup vs baseline: 1.4169x; 1.0568x over previous
#include <cuda_runtime.h>
#include <math.h>

// Problem constants
#define D   784
#define H   500
#define HP  512
#define B   512
#define S   28           // segments (784 = 28*28)
#define L   28           // steps per segment
#define BD  (B*D)

#define TPB      256
#define WPB      8
#define RPW      4       // rows per warp in k_scan
#define ROWS_PB  (WPB*RPW)   // 32
#define CH       2       // dot-reduction chunk

typedef unsigned long long u64;

// Static device scratch
__device__ float g_WT[D*HP];     // W^T padded: [d][h]
__device__ float g_Vp[D*HP];     // V padded:   [d][h]
__device__ float g_c [HP];
__device__ float g_A [B*S*HP];   // partials then checkpoints: [b][s][h]

// ---- packed f32x2 helpers -------------------------------------------------
__device__ __forceinline__ u64 ffma2(u64 a, u64 b, u64 c) {
    u64 d;
    asm("fma.rn.f32x2 %0, %1, %2, %3;" : "=l"(d) : "l"(a), "l"(b), "l"(c));
    return d;
}
__device__ __forceinline__ u64 relu2(u64 a) {
    u64 r;
    asm("{\n\t.reg .f32 lo, hi;\n\t"
        "mov.b64 {lo, hi}, %1;\n\t"
        "max.f32 lo, lo, 0f00000000;\n\t"
        "max.f32 hi, hi, 0f00000000;\n\t"
        "mov.b64 %0, {lo, hi};\n\t}" : "=l"(r) : "l"(a));
    return r;
}
__device__ __forceinline__ u64 pack2(float x) {
    u64 r;
    asm("mov.b64 %0, {%1, %1};" : "=l"(r) : "f"(x));
    return r;
}
__device__ __forceinline__ float hadd2(u64 a) {
    float lo, hi;
    asm("mov.b64 {%0, %1}, %2;" : "=f"(lo), "=f"(hi) : "l"(a));
    return lo + hi;
}

// ---------------------------------------------------------------------------
// K0a: pad V rows 500->512, pad c. Fully coalesced.
// ---------------------------------------------------------------------------
__global__ void k_packV(const float* __restrict__ V,
                        const float* __restrict__ c) {
    int d = blockIdx.x;          // 0..783
    int t = threadIdx.x;         // 0..511
    g_Vp[d*HP + t] = (t < H) ? V[d*H + t] : 0.0f;
    if (d == 0) g_c[t] = (t < H) ? c[t] : 0.0f;
}

// ---------------------------------------------------------------------------
// K0b: tiled transpose W [H,D] -> g_WT [D,HP]. 32x32 tiles via smem.
// ---------------------------------------------------------------------------
__global__ void k_packW(const float* __restrict__ W) {
    __shared__ float tile[32][33];
    int d0 = blockIdx.x * 32;
    int h0 = blockIdx.y * 32;
    int tx = threadIdx.x;        // 0..31
    int ty = threadIdx.y;        // 0..7
    #pragma unroll
    for (int i = 0; i < 4; i++) {
        int h = h0 + ty + 8*i;
        int d = d0 + tx;
        float v = 0.0f;
        if (h < H && d < D) v = W[h*D + d];
        tile[ty + 8*i][tx] = v;
    }
    __syncthreads();
    #pragma unroll
    for (int i = 0; i < 4; i++) {
        int d = d0 + ty + 8*i;
        int h = h0 + tx;
        if (d < D) g_WT[d*HP + h] = tile[tx][ty + 8*i];
    }
}

// ---------------------------------------------------------------------------
// K1: partial GEMM. Block = (segment s in 0..26, 32-row tile).
//     P_s[rows, :] = X[rows, s*28:(s+1)*28] @ W[s*28:(s+1)*28, :]
//     Stored at g_A[row][s][:]  (layout [b][s][h]).
// ---------------------------------------------------------------------------
__global__ __launch_bounds__(256)
void k_partial(const float* __restrict__ x) {
    int s  = blockIdx.x;         // 0..26
    int rb = blockIdx.y;         // 0..15
    int t  = threadIdx.x;        // 0..255 : h-pair index
    int rowbase = rb * 32;

    __shared__ u64 sxp[32 * L];  // pre-packed x (f32x2 duplicated)
    for (int i = t; i < 32 * L; i += 256) {
        int r = i / L, j = i - r * L;
        sxp[i] = pack2(x[(rowbase + r)*D + s*L + j]);
    }
    __syncthreads();

    u64 acc[32];
    #pragma unroll
    for (int r = 0; r < 32; r++) acc[r] = 0ull;

    const u64* W1 = (const u64*)g_WT;   // 256 pairs per d-row
    #pragma unroll 2
    for (int j = 0; j < L; j++) {
        u64 wv = W1[(size_t)(s*L + j)*256 + t];
        #pragma unroll
        for (int r = 0; r < 32; r++)
            acc[r] = ffma2(sxp[r*L + j], wv, acc[r]);   // x in {0,1}: exact
    }

    u64* A1 = (u64*)g_A;
    #pragma unroll
    for (int r = 0; r < 32; r++)
        A1[((size_t)(rowbase + r)*S + s)*256 + t] = acc[r];
}

// ---------------------------------------------------------------------------
// K2: prefix over segments, scalar threads: one per (b,h).
//     A[b][s][h] = c[h] + sum_{t<s} P_t[b][h]   (in-place; slot 0 gets c).
//     262144 threads; per-thread chain walks 2KB-strided 56KB region.
// ---------------------------------------------------------------------------
__global__ __launch_bounds__(256)
void k_prefix() {
    int g = blockIdx.x * 256 + threadIdx.x;   // 0..262143
    int h = g & (HP - 1);
    int b = g >> 9;
    float v = g_c[h];
    float* base = g_A + (size_t)b*S*HP + h;
    #pragma unroll
    for (int s = 0; s < S; s++) {
        float p = base[s*HP];
        base[s*HP] = v;
        v += p;
    }
}

// ---------------------------------------------------------------------------
// K3: the scan. Block = (segment, 32 rows). Warp = 4 rows.
// Lane owns 16 floats (8 u64) of the 512-wide state per row.
// ---------------------------------------------------------------------------
__global__ __launch_bounds__(TPB, 2)
void k_scan(const float* __restrict__ x,
            const float* __restrict__ u,
            const float* __restrict__ bvec,
            float* __restrict__ out) {
    int s    = blockIdx.x;       // 0..27
    int rb   = blockIdx.y;       // 0..15
    int tid  = threadIdx.x;
    int w    = tid >> 5;
    int lane = tid & 31;
    int rowbase = rb * ROWS_PB;

    __shared__ u64   sxp[ROWS_PB * L];   // pre-packed x
    __shared__ float su [ROWS_PB * L];
    __shared__ float sb [L];
    __shared__ float sl [ROWS_PB * L];
    __shared__ float sxs[ROWS_PB * L];

    for (int i = tid; i < ROWS_PB * L; i += TPB) {
        int r = i / L, j = i - r * L;
        sxp[i] = pack2(x[(rowbase + r)*D + s*L + j]);
        su [i] = u[(rowbase + r)*D + s*L + j];
    }
    for (int i = tid; i < L; i += TPB) sb[i] = bvec[s*L + i];
    __syncthreads();

    int r0 = rowbase + w * RPW;
    const ulonglong2* A2 = (const ulonglong2*)g_A;
    u64 a[RPW][8];
    #pragma unroll
    for (int r = 0; r < RPW; r++) {
        #pragma unroll
        for (int k = 0; k < 4; k++) {
            ulonglong2 q = A2[((size_t)(r0 + r)*S + s)*128 + lane + 32*k];
            a[r][2*k] = q.x; a[r][2*k+1] = q.y;
        }
    }

    const ulonglong2* V2 = (const ulonglong2*)g_Vp;
    const ulonglong2* W2 = (const ulonglong2*)g_WT;
    const u64* sxw = sxp + (w*RPW)*L;

    int dbase = s * L;
    for (int c2 = 0; c2 < L/CH; c2++) {
        float dt[RPW][CH];
        #pragma unroll
        for (int jj = 0; jj < CH; jj++) {
            int j = c2*CH + jj;
            int d = dbase + j;
            const ulonglong2* Vr = V2 + (size_t)d*128;
            const ulonglong2* Wr = W2 + (size_t)d*128;
            u64 xx[RPW];
            #pragma unroll
            for (int r = 0; r < RPW; r++) xx[r] = sxw[r*L + j];

            u64 dp[RPW];
            #pragma unroll
            for (int r = 0; r < RPW; r++) dp[r] = 0ull;

            #pragma unroll
            for (int k = 0; k < 4; k++) {
                ulonglong2 vq = Vr[lane + 32*k];
                ulonglong2 wq = Wr[lane + 32*k];
                #pragma unroll
                for (int r = 0; r < RPW; r++) {
                    dp[r] = ffma2(relu2(a[r][2*k  ]), vq.x, dp[r]);
                    dp[r] = ffma2(relu2(a[r][2*k+1]), vq.y, dp[r]);
                    a[r][2*k  ] = ffma2(xx[r], wq.x, a[r][2*k  ]);
                    a[r][2*k+1] = ffma2(xx[r], wq.y, a[r][2*k+1]);
                }
            }
            #pragma unroll
            for (int r = 0; r < RPW; r++) dt[r][jj] = hadd2(dp[r]);
        }

        // 8 independent butterfly chains
        #pragma unroll
        for (int off = 16; off > 0; off >>= 1) {
            #pragma unroll
            for (int r = 0; r < RPW; r++)
                #pragma unroll
                for (int jj = 0; jj < CH; jj++)
                    dt[r][jj] += __shfl_xor_sync(0xffffffffu, dt[r][jj], off);
        }

        // epilogue: lane k (<8) handles (row k>>1, step k&1)
        if (lane < RPW*CH) {
            int r  = lane >> 1;
            int jj = lane & 1;
            float dv = dt[0][0];
            dv = (lane == 1) ? dt[0][1] : dv;
            dv = (lane == 2) ? dt[1][0] : dv;
            dv = (lane == 3) ? dt[1][1] : dv;
            dv = (lane == 4) ? dt[2][0] : dv;
            dv = (lane == 5) ? dt[2][1] : dv;
            dv = (lane == 6) ? dt[3][0] : dv;
            dv = (lane == 7) ? dt[3][1] : dv;
            int j  = c2*CH + jj;
            int ri = w*RPW + r;
            float lv = dv + sb[j];
            float uu = su[ri*L + j];
            float e  = expf(-lv);
            float xs = (fmaf(uu, e, uu) < 1.0f) ? 1.0f : 0.0f;
            sl [ri*L + j] = lv;
            sxs[ri*L + j] = xs;
        }
    }

    __syncthreads();
    for (int i = tid; i < ROWS_PB * L; i += TPB) {
        int r = i / L, j = i - r * L;
        size_t g = (size_t)(rowbase + r)*D + s*L + j;
        out[g]      = sl[i];
        out[BD + g] = sxs[i];
    }
}

// ---------------------------------------------------------------------------
// Inputs: x[B,D], u[B,D], W[H,D], c[H], V[D,H], b[D]
// Output: [ l (B*D) | x_sample (B*D) ]
// ---------------------------------------------------------------------------
extern "C" void kernel_launch(void* const* d_in, const int* in_sizes, int n_in,
                              void* d_out, int out_size) {
    (void)in_sizes; (void)n_in; (void)out_size;
    const float* x    = (const float*)d_in[0];
    const float* u    = (const float*)d_in[1];
    const float* W    = (const float*)d_in[2];
    const float* c    = (const float*)d_in[3];
    const float* V    = (const float*)d_in[4];
    const float* bvec = (const float*)d_in[5];
    float* out = (float*)d_out;

    k_packV  <<<D, HP>>>(V, c);
    k_packW  <<<dim3((D+31)/32, HP/32), dim3(32, 8)>>>(W);
    k_partial<<<dim3(S-1, B/32), 256>>>(x);
    k_prefix <<<(B*HP)/256, 256>>>();
    k_scan   <<<dim3(S, B/ROWS_PB), TPB>>>(x, u, bvec, out);
}